// round 4
// baseline (speedup 1.0000x reference)
#include <cuda_runtime.h>
#include <cstdint>

#define K_CODES 8192
#define CDIM    256
#define SPAT    4096
#define NROWS   32768            // 8 * 4096
#define OUT_ELEMS (8 * CDIM * SPAT)

typedef unsigned long long ull;

// ---- scratch (no allocations allowed) ----
__device__ float  g_cbT[CDIM * K_CODES];   // codebook transposed [c][k], 8 MB
__device__ float  g_cbn[K_CODES];          // ||c_k||^2 (fp32)
__device__ float  g_zn[NROWS];             // ||z_n||^2 (fp32)
__device__ int    g_idx[NROWS];
__device__ double g_loss;

// packed f32x2 FMA: two independent rn fp32 FMAs per instruction (FFMA2)
__device__ __forceinline__ void fma2(ull& acc, ull a, ull b) {
    asm("fma.rn.f32x2 %0, %1, %2, %0;" : "+l"(acc) : "l"(a), "l"(b));
}
__device__ __forceinline__ ull splat2(float v) {
    ull r;
    unsigned u = __float_as_uint(v);
    asm("mov.b64 %0, {%1, %1};" : "=l"(r) : "r"(u));
    return r;
}
__device__ __forceinline__ float2 unpack2(ull v) {
    float2 r;
    r.x = __uint_as_float((unsigned)(v & 0xffffffffull));
    r.y = __uint_as_float((unsigned)(v >> 32));
    return r;
}

// ---------------- K1: codebook transpose + norms ----------------
__global__ void k_cbprep(const float* __restrict__ cb) {
    int k = blockIdx.x;
    int c = threadIdx.x;
    float v = cb[k * CDIM + c];
    g_cbT[(size_t)c * K_CODES + k] = v;
    float s = v * v;
    #pragma unroll
    for (int o = 16; o > 0; o >>= 1) s += __shfl_xor_sync(~0u, s, o);
    __shared__ float ws[8];
    if ((c & 31) == 0) ws[c >> 5] = s;
    __syncthreads();
    if (c == 0) {
        float t = 0.f;
        #pragma unroll
        for (int i = 0; i < 8; i++) t += ws[i];
        g_cbn[k] = t;
    }
}

// ---------------- K2: z row norms ----------------
__global__ void k_zn(const float* __restrict__ z) {
    int n = blockIdx.x * 256 + threadIdx.x;
    int b = n >> 12, p = n & 4095;
    const float* zp = z + (size_t)b * CDIM * SPAT + p;
    float s = 0.f;
    #pragma unroll 8
    for (int c = 0; c < CDIM; c++) {
        float v = zp[(size_t)c * SPAT];
        s = fmaf(v, v, s);
    }
    g_zn[n] = s;
}

// ---------------- K0: zero loss accumulator ----------------
__global__ void k_zero() { g_loss = 0.0; }

// ---------------- K3: distance GEMM + argmin (FFMA2 inner product) ----------
// grid = 256 CTAs (128 rows each), 256 threads; each CTA scans all 8192 codes.
__global__ void __launch_bounds__(256, 2)
k_argmin(const float* __restrict__ z) {
    __shared__ float As[2][8][128];
    __shared__ float Bs[2][8][128];

    int tid = threadIdx.x;
    int tx = tid & 15, ty = tid >> 4;
    int n0 = blockIdx.x * 128;
    int b = n0 >> 12, p0 = n0 & 4095;
    const float* zbase = z + (size_t)b * CDIM * SPAT + p0;

    int lci = tid >> 5;            // 0..7  (c within chunk)
    int lni = (tid & 31) << 2;     // 0..124 (n/k within tile, float4)

    float best_d[8];
    int   best_k[8];
    float Zr[8];
    #pragma unroll
    for (int i = 0; i < 8; i++) {
        best_d[i] = 3.4e38f; best_k[i] = 0;
        Zr[i] = g_zn[n0 + ty * 8 + i];
    }

    // acc2[i][jj] holds (j=2*jj, j=2*jj+1) packed as f32x2
    ull acc2[8][4];
    #pragma unroll
    for (int i = 0; i < 8; i++)
        #pragma unroll
        for (int j = 0; j < 4; j++) acc2[i][j] = 0ull;

    #pragma unroll 1
    for (int kt = 0; kt < K_CODES / 128; kt++) {
        int k0 = kt * 128;

        float4 aReg = *(const float4*)(zbase + (size_t)lci * SPAT + lni);
        float4 bReg = *(const float4*)(g_cbT + (size_t)lci * K_CODES + k0 + lni);
        *(float4*)&As[0][lci][lni] = aReg;
        *(float4*)&Bs[0][lci][lni] = bReg;
        __syncthreads();

        #pragma unroll 1
        for (int cs = 0; cs < 32; cs++) {
            int cur = cs & 1;
            if (cs < 31) {
                int c0 = (cs + 1) * 8;
                aReg = *(const float4*)(zbase + (size_t)(c0 + lci) * SPAT + lni);
                bReg = *(const float4*)(g_cbT + (size_t)(c0 + lci) * K_CODES + k0 + lni);
            }
            #pragma unroll
            for (int cc = 0; cc < 8; cc++) {
                float a[8];
                *(float4*)&a[0] = *(float4*)&As[cur][cc][ty * 8];
                *(float4*)&a[4] = *(float4*)&As[cur][cc][ty * 8 + 4];
                ulonglong2 bA = *(const ulonglong2*)&Bs[cur][cc][tx * 8];
                ulonglong2 bB = *(const ulonglong2*)&Bs[cur][cc][tx * 8 + 4];
                #pragma unroll
                for (int i = 0; i < 8; i++) {
                    ull aa = splat2(a[i]);
                    fma2(acc2[i][0], aa, bA.x);
                    fma2(acc2[i][1], aa, bA.y);
                    fma2(acc2[i][2], aa, bB.x);
                    fma2(acc2[i][3], aa, bB.y);
                }
            }
            if (cs < 31) {
                int nxt = cur ^ 1;
                *(float4*)&As[nxt][lci][lni] = aReg;
                *(float4*)&Bs[nxt][lci][lni] = bReg;
            }
            __syncthreads();
        }

        // epilogue: d = fl( fl(Z + cbn_k) - fl(2*dot) ), argmin first-index
        float4 c0v = *(const float4*)(g_cbn + k0 + tx * 8);
        float4 c1v = *(const float4*)(g_cbn + k0 + tx * 8 + 4);
        float cbn8[8] = {c0v.x, c0v.y, c0v.z, c0v.w, c1v.x, c1v.y, c1v.z, c1v.w};
        #pragma unroll
        for (int i = 0; i < 8; i++) {
            float Z = Zr[i];
            #pragma unroll
            for (int jj = 0; jj < 4; jj++) {
                float2 dot = unpack2(acc2[i][jj]);
                int j0 = 2 * jj;
                float t1 = __fadd_rn(Z, cbn8[j0]);
                float d  = __fmaf_rn(-2.0f, dot.x, t1);
                if (d < best_d[i]) { best_d[i] = d; best_k[i] = k0 + tx * 8 + j0; }
                float t2 = __fadd_rn(Z, cbn8[j0 + 1]);
                float d2 = __fmaf_rn(-2.0f, dot.y, t2);
                if (d2 < best_d[i]) { best_d[i] = d2; best_k[i] = k0 + tx * 8 + j0 + 1; }
                acc2[i][jj] = 0ull;
            }
        }
    }

    // reduce across the 16 tx lanes (same rows), lower index wins ties
    #pragma unroll
    for (int i = 0; i < 8; i++) {
        float d = best_d[i];
        int   k = best_k[i];
        #pragma unroll
        for (int o = 8; o > 0; o >>= 1) {
            float od = __shfl_xor_sync(~0u, d, o, 16);
            int   ok = __shfl_xor_sync(~0u, k, o, 16);
            if (od < d || (od == d && ok < d + (ok < k))) {}  // placeholder avoided
            if (od < d || (od == d && ok < k)) { d = od; k = ok; }
        }
        if (tx == 0) g_idx[n0 + ty * 8 + i] = k;
    }
}

// ---------------- K4: gather output + loss partial ----------------
__global__ void k_out(const float* __restrict__ z, const float* __restrict__ cb,
                      float* __restrict__ out, int out_size) {
    int n = blockIdx.x * 256 + threadIdx.x;
    int b = n >> 12, p = n & 4095;
    int myk = g_idx[n];
    const float* crow = cb + (size_t)myk * CDIM;
    const float* zp = z + (size_t)b * CDIM * SPAT + p;
    float* op = out + (size_t)b * CDIM * SPAT + p;
    double ls = 0.0;
    #pragma unroll 4
    for (int c = 0; c < CDIM; c++) {
        float q  = crow[c];
        float zv = zp[(size_t)c * SPAT];
        op[(size_t)c * SPAT] = q;           // z_q_st == z_q numerically
        float dlt = q - zv;
        ls += (double)dlt * (double)dlt;
    }
    #pragma unroll
    for (int o = 16; o > 0; o >>= 1) ls += __shfl_xor_sync(~0u, ls, o);
    __shared__ double ws[8];
    if ((threadIdx.x & 31) == 0) ws[threadIdx.x >> 5] = ls;
    __syncthreads();
    if (threadIdx.x == 0) {
        double t = 0.0;
        #pragma unroll
        for (int i = 0; i < 8; i++) t += ws[i];
        atomicAdd(&g_loss, t);
    }
    if (out_size >= OUT_ELEMS + 1 + NROWS)
        out[OUT_ELEMS + 1 + n] = (float)myk;
}

// ---------------- K5: finalize loss ----------------
__global__ void k_fin(float* __restrict__ out, int out_size) {
    if (out_size >= OUT_ELEMS + 1)
        out[OUT_ELEMS] = (float)((2.0 * g_loss) / (double)OUT_ELEMS);
}

extern "C" void kernel_launch(void* const* d_in, const int* in_sizes, int n_in,
                              void* d_out, int out_size) {
    const float* z  = (const float*)d_in[0];
    const float* cb = (const float*)d_in[1];
    if (n_in >= 2 && in_sizes[0] == K_CODES * CDIM) {  // tolerate swapped order
        z  = (const float*)d_in[1];
        cb = (const float*)d_in[0];
    }
    float* out = (float*)d_out;

    k_cbprep<<<K_CODES, 256>>>(cb);
    k_zn<<<NROWS / 256, 256>>>(z);
    k_zero<<<1, 1>>>();
    k_argmin<<<NROWS / 128, 256>>>(z);
    k_out<<<NROWS / 256, 256>>>(z, cb, out, out_size);
    k_fin<<<1, 1>>>(out, out_size);
}

// round 11
// speedup vs baseline: 1.3939x; 1.3939x over previous
#include <cuda_runtime.h>
#include <cuda_bf16.h>
#include <cstdint>

#define K_CODES 8192
#define CDIM    256
#define SPAT    4096
#define NROWS   32768
#define OUT_ELEMS (8 * CDIM * SPAT)

#define ROWS_CTA 64
#define T_TILES  (K_CODES / 32)       // 256 tiles of 32 codes
#define A_SPLIT  (ROWS_CTA * 512)     // 32768 B per split (row stride 512B)
#define A_BYTES  (3 * A_SPLIT)        // 98304
#define BP_SPLIT (32 * 512)           // 16384 B per split panel
#define BPANEL   (3 * BP_SPLIT)       // 49152
#define SM_B0    A_BYTES
#define SM_B1    (A_BYTES + BPANEL)
#define SM_CBN   (A_BYTES + 2 * BPANEL)      // 2 x 128 B
#define SMEM_TOTAL (SM_CBN + 256)

typedef unsigned long long ull;

// ---- scratch ----
__device__ uint4  g_c0[K_CODES * CDIM / 8];   // bf16 splits, [code][k] contiguous
__device__ uint4  g_c1[K_CODES * CDIM / 8];
__device__ uint4  g_c2[K_CODES * CDIM / 8];
__device__ float  g_cbn[K_CODES];
__device__ float  g_zn[NROWS];
__device__ int    g_cand[NROWS * 16];         // top-2 per owner-lane, 16 per row
__device__ int    g_idx[NROWS];
__device__ double g_loss;

// ---------------- PTX helpers (baseline ISA only) ----------------
__device__ __forceinline__ uint32_t smem_u32(const void* p) {
    uint32_t a;
    asm("{ .reg .u64 t; cvta.to.shared.u64 t, %1; cvt.u32.u64 %0, t; }" : "=r"(a) : "l"(p));
    return a;
}
#define CP16(dst, src) asm volatile("cp.async.cg.shared.global [%0], [%1], 16;" :: "r"(dst), "l"(src))
#define CP_COMMIT()    asm volatile("cp.async.commit_group;" ::: "memory")
#define CP_WAIT0()     asm volatile("cp.async.wait_group 0;" ::: "memory")

__device__ __forceinline__ void ldsm4(uint32_t& r0, uint32_t& r1, uint32_t& r2, uint32_t& r3,
                                      uint32_t addr) {
    asm volatile("ldmatrix.sync.aligned.m8n8.x4.shared.b16 {%0,%1,%2,%3}, [%4];"
                 : "=r"(r0), "=r"(r1), "=r"(r2), "=r"(r3) : "r"(addr));
}
__device__ __forceinline__ void mma_bf16(float* c, uint32_t a0, uint32_t a1, uint32_t a2,
                                         uint32_t a3, uint32_t b0, uint32_t b1) {
    asm volatile(
        "mma.sync.aligned.m16n8k16.row.col.f32.bf16.bf16.f32 "
        "{%0,%1,%2,%3}, {%4,%5,%6,%7}, {%8,%9}, {%0,%1,%2,%3};"
        : "+f"(c[0]), "+f"(c[1]), "+f"(c[2]), "+f"(c[3])
        : "r"(a0), "r"(a1), "r"(a2), "r"(a3), "r"(b0), "r"(b1));
}

// ---------------- K1: codebook splits + norms ----------------
__global__ void k_cbprep(const float* __restrict__ cb) {
    int k = blockIdx.x, c = threadIdx.x;
    float v = cb[k * CDIM + c];
    __nv_bfloat16 c0 = __float2bfloat16_rn(v);
    float r1 = v - __bfloat162float(c0);
    __nv_bfloat16 c1 = __float2bfloat16_rn(r1);
    float r2 = r1 - __bfloat162float(c1);
    __nv_bfloat16 c2 = __float2bfloat16_rn(r2);
    ((__nv_bfloat16*)g_c0)[k * CDIM + c] = c0;
    ((__nv_bfloat16*)g_c1)[k * CDIM + c] = c1;
    ((__nv_bfloat16*)g_c2)[k * CDIM + c] = c2;
    float s = v * v;
    #pragma unroll
    for (int o = 16; o > 0; o >>= 1) s += __shfl_xor_sync(~0u, s, o);
    __shared__ float ws[8];
    if ((c & 31) == 0) ws[c >> 5] = s;
    __syncthreads();
    if (c == 0) {
        float t = 0.f;
        #pragma unroll
        for (int i = 0; i < 8; i++) t += ws[i];
        g_cbn[k] = t;
    }
}

// ---------------- K2: z row norms ----------------
__global__ void k_zn(const float* __restrict__ z) {
    int n = blockIdx.x * 256 + threadIdx.x;
    int b = n >> 12, p = n & 4095;
    const float* zp = z + (size_t)b * CDIM * SPAT + p;
    float s = 0.f;
    #pragma unroll 8
    for (int c = 0; c < CDIM; c++) {
        float v = zp[(size_t)c * SPAT];
        s = fmaf(v, v, s);
    }
    g_zn[n] = s;
}

__global__ void k_zero() { g_loss = 0.0; }

// ---- issue one B panel (tile t) + its cbn slice via cp.async ----
__device__ __forceinline__ void issue_panel(int t, uint32_t dstB, uint32_t dstCbn, int tid) {
    #pragma unroll
    for (int j = 0; j < 12; j++) {
        int id = j * 256 + tid;             // 0..3071
        int sp = id >> 10;
        int rem = id & 1023;
        int code = rem >> 5;
        int kc = (rem & 31) << 4;           // byte offset in 512B row
        const char* base = (sp == 0) ? (const char*)g_c0
                         : (sp == 1) ? (const char*)g_c1 : (const char*)g_c2;
        const char* src = base + (size_t)(t * 32 + code) * 512 + kc;
        uint32_t dst = dstB + sp * BP_SPLIT + code * 512 + (kc ^ ((code & 7) << 4));
        CP16(dst, src);
    }
    if (tid < 8)
        CP16(dstCbn + tid * 16, (const char*)g_cbn + (size_t)t * 128 + tid * 16);
}

#define UPD(dv, col, d1, k1, d2, k2) \
    do { if ((dv) < (d1)) { d2 = d1; k2 = k1; d1 = (dv); k1 = (col); } \
         else if ((dv) < (d2)) { d2 = (dv); k2 = (col); } } while (0)

// ---------------- K3: HMMA distance GEMM -> top-2 candidates/lane ----------
__global__ void __launch_bounds__(256, 1)
k_argmin(const float* __restrict__ z) {
    extern __shared__ char smem[];
    uint32_t sb = smem_u32(smem);
    int tid = threadIdx.x, w = tid >> 5, lane = tid & 31;
    int n0 = blockIdx.x * ROWS_CTA;
    int b = n0 >> 12, p0 = n0 & 4095;

    // preload panel 0 + cbn0
    issue_panel(0, sb + SM_B0, sb + SM_CBN, tid);
    CP_COMMIT();

    // ---- A prep: 64 rows x 256 k, 3-way bf16 split, swizzled SMEM ----
    {
        int row = tid & 63, kg = tid >> 6;
        const float* zp = z + ((size_t)b * CDIM + kg * 64) * SPAT + p0 + row;
        uint32_t sw = (uint32_t)(row & 7) << 4;
        char* ab = smem + row * 512;
        #pragma unroll 4
        for (int kk = 0; kk < 64; kk += 2) {
            float v0 = zp[(size_t)kk * SPAT];
            float v1 = zp[(size_t)(kk + 1) * SPAT];
            __nv_bfloat16 a0 = __float2bfloat16_rn(v0);
            float ra = v0 - __bfloat162float(a0);
            __nv_bfloat16 a1 = __float2bfloat16_rn(ra);
            float ra2 = ra - __bfloat162float(a1);
            __nv_bfloat16 a2 = __float2bfloat16_rn(ra2);
            __nv_bfloat16 c0 = __float2bfloat16_rn(v1);
            float rc = v1 - __bfloat162float(c0);
            __nv_bfloat16 c1 = __float2bfloat16_rn(rc);
            float rc2 = rc - __bfloat162float(c1);
            __nv_bfloat16 c2 = __float2bfloat16_rn(rc2);
            uint32_t off = (uint32_t)((kg * 64 + kk) * 2) ^ sw;
            *(uint32_t*)(ab + off) =
                (uint32_t)__bfloat16_as_ushort(a0) | ((uint32_t)__bfloat16_as_ushort(c0) << 16);
            *(uint32_t*)(ab + A_SPLIT + off) =
                (uint32_t)__bfloat16_as_ushort(a1) | ((uint32_t)__bfloat16_as_ushort(c1) << 16);
            *(uint32_t*)(ab + 2 * A_SPLIT + off) =
                (uint32_t)__bfloat16_as_ushort(a2) | ((uint32_t)__bfloat16_as_ushort(c2) << 16);
        }
    }

    // per-lane fragment bases
    int rowA = 16 * (w & 3) + (lane & 7) + ((lane >> 3) & 1) * 8;
    uint32_t aRow = sb + rowA * 512;
    uint32_t swA = (uint32_t)(rowA & 7) << 4;
    int rowB = 16 * (w >> 2) + (lane & 7) + ((lane >> 3) & 1) * 8;
    uint32_t swB = (uint32_t)(rowB & 7) << 4;
    uint32_t kadd = (uint32_t)(lane >> 4) * 16;
    int half = w >> 2;

    int rA = 16 * (w & 3) + (lane >> 2);
    float ZA = g_zn[n0 + rA], ZB = g_zn[n0 + rA + 8];
    float dA1 = 3.4e38f, dA2 = 3.4e38f, dB1 = 3.4e38f, dB2 = 3.4e38f;
    int   kA1 = 0, kA2 = 0, kB1 = 0, kB2 = 0;

    const int cSA[6] = {0, 0, 1, 0, 1, 2};
    const int cSB[6] = {0, 1, 0, 2, 1, 0};

    float acc[2][4];
    #pragma unroll
    for (int i = 0; i < 2; i++)
        #pragma unroll
        for (int j = 0; j < 4; j++) acc[i][j] = 0.f;

    #pragma unroll 1
    for (int t = 0; t < T_TILES; t++) {
        int buf = t & 1;
        CP_WAIT0();
        __syncthreads();
        if (t + 1 < T_TILES) {
            issue_panel(t + 1, sb + (buf ? SM_B0 : SM_B1), sb + SM_CBN + (buf ^ 1) * 128, tid);
            CP_COMMIT();
        }
        uint32_t Bb = sb + (buf ? SM_B1 : SM_B0);

        #pragma unroll 1
        for (int p = 0; p < 6; p++) {
            uint32_t aSp = aRow + cSA[p] * A_SPLIT;
            uint32_t bSp = Bb + cSB[p] * BP_SPLIT + rowB * 512;
            #pragma unroll
            for (int ks = 0; ks < 16; ks++) {
                uint32_t colA = ((uint32_t)(ks * 32) + kadd) ^ swA;
                uint32_t colB = ((uint32_t)(ks * 32) + kadd) ^ swB;
                uint32_t a0, a1, a2, a3, b0, b1, b2, b3;
                ldsm4(a0, a1, a2, a3, aSp + colA);
                ldsm4(b0, b1, b2, b3, bSp + colB);
                mma_bf16(acc[0], a0, a1, a2, a3, b0, b2);
                mma_bf16(acc[1], a0, a1, a2, a3, b1, b3);
            }
        }

        // ---- epilogue: approx d, top-2 per lane ----
        {
            const float* cbn = (const float*)(smem + SM_CBN + buf * 128);
            int colp = 16 * half + (lane & 3) * 2;
            int cb0 = t * 32 + colp;
            #pragma unroll
            for (int nt = 0; nt < 2; nt++) {
                float cnx = cbn[colp + nt * 8];
                float cny = cbn[colp + nt * 8 + 1];
                int col = cb0 + nt * 8;
                float d;
                d = __fmaf_rn(-2.f, acc[nt][0], __fadd_rn(ZA, cnx));
                UPD(d, col, dA1, kA1, dA2, kA2);
                d = __fmaf_rn(-2.f, acc[nt][1], __fadd_rn(ZA, cny));
                UPD(d, col + 1, dA1, kA1, dA2, kA2);
                d = __fmaf_rn(-2.f, acc[nt][2], __fadd_rn(ZB, cnx));
                UPD(d, col, dB1, kB1, dB2, kB2);
                d = __fmaf_rn(-2.f, acc[nt][3], __fadd_rn(ZB, cny));
                UPD(d, col + 1, dB1, kB1, dB2, kB2);
                acc[nt][0] = acc[nt][1] = acc[nt][2] = acc[nt][3] = 0.f;
            }
        }
    }

    // ---- write candidates: 8 per row-half per warp, 16 per row total ----
    {
        int baseA = (n0 + rA) * 16 + half * 8 + (lane & 3) * 2;
        g_cand[baseA]     = kA1;
        g_cand[baseA + 1] = kA2;
        int baseB = (n0 + rA + 8) * 16 + half * 8 + (lane & 3) * 2;
        g_cand[baseB]     = kB1;
        g_cand[baseB + 1] = kB2;
    }
}

// ---------------- K3b: exact fp32 refinement over 16 candidates/row --------
// Replicates the R2-proven semantics: sequential k-ascending fmaf dot,
// d = fmaf(-2, dot, fl(Zn + cbn)), argmin with lowest-index tie-break.
__global__ void __launch_bounds__(256, 2)
k_refine(const float* __restrict__ z, const float* __restrict__ cb) {
    __shared__ float zs[16][256];
    int tid = threadIdx.x;
    int n0 = blockIdx.x * 16;
    int b = n0 >> 12, p0 = n0 & 4095;

    // stage 16 z rows into smem (coalesced over p)
    for (int i = tid; i < 16 * 256; i += 256) {
        int c = i >> 4, pr = i & 15;
        zs[pr][c] = z[((size_t)b * CDIM + c) * SPAT + p0 + pr];
    }
    __syncthreads();

    int r = tid >> 4;          // row within block
    int ci = tid & 15;         // candidate slot
    int n = n0 + r;
    int k = g_cand[n * 16 + ci];

    const float4* cbr = (const float4*)(cb + (size_t)k * CDIM);
    const float4* zr = (const float4*)zs[r];
    float acc = 0.f;
    #pragma unroll 8
    for (int c4 = 0; c4 < 64; c4++) {
        float4 bv = cbr[c4];
        float4 av = zr[c4];
        acc = fmaf(av.x, bv.x, acc);
        acc = fmaf(av.y, bv.y, acc);
        acc = fmaf(av.z, bv.z, acc);
        acc = fmaf(av.w, bv.w, acc);
    }
    float t1 = __fadd_rn(g_zn[n], g_cbn[k]);
    float d = __fmaf_rn(-2.f, acc, t1);

    // reduce across the 16 candidate lanes (lowest index wins ties)
    #pragma unroll
    for (int o = 8; o > 0; o >>= 1) {
        float od = __shfl_xor_sync(~0u, d, o, 16);
        int   ok = __shfl_xor_sync(~0u, k, o, 16);
        if (od < d || (od == d && ok < k)) { d = od; k = ok; }
    }
    if (ci == 0) g_idx[n] = k;
}

// ---------------- K4: gather output + loss ----------------
__global__ void k_out(const float* __restrict__ z, const float* __restrict__ cb,
                      float* __restrict__ out, int out_size) {
    int n = blockIdx.x * 256 + threadIdx.x;
    int b = n >> 12, p = n & 4095;
    int myk = g_idx[n];
    const float* crow = cb + (size_t)myk * CDIM;
    const float* zp = z + (size_t)b * CDIM * SPAT + p;
    float* op = out + (size_t)b * CDIM * SPAT + p;
    double ls = 0.0;
    #pragma unroll 4
    for (int c = 0; c < CDIM; c++) {
        float q = crow[c];
        float zv = zp[(size_t)c * SPAT];
        op[(size_t)c * SPAT] = q;
        float dlt = q - zv;
        ls += (double)dlt * (double)dlt;
    }
    #pragma unroll
    for (int o = 16; o > 0; o >>= 1) ls += __shfl_xor_sync(~0u, ls, o);
    __shared__ double ws[8];
    if ((threadIdx.x & 31) == 0) ws[threadIdx.x >> 5] = ls;
    __syncthreads();
    if (threadIdx.x == 0) {
        double t = 0.0;
        #pragma unroll
        for (int i = 0; i < 8; i++) t += ws[i];
        atomicAdd(&g_loss, t);
    }
    if (out_size >= OUT_ELEMS + 1 + NROWS)
        out[OUT_ELEMS + 1 + n] = (float)myk;
}

__global__ void k_fin(float* __restrict__ out, int out_size) {
    if (out_size >= OUT_ELEMS + 1)
        out[OUT_ELEMS] = (float)((2.0 * g_loss) / (double)OUT_ELEMS);
}

extern "C" void kernel_launch(void* const* d_in, const int* in_sizes, int n_in,
                              void* d_out, int out_size) {
    const float* z  = (const float*)d_in[0];
    const float* cb = (const float*)d_in[1];
    if (n_in >= 2 && in_sizes[0] == K_CODES * CDIM) {
        z  = (const float*)d_in[1];
        cb = (const float*)d_in[0];
    }
    float* out = (float*)d_out;

    cudaFuncSetAttribute(k_argmin, cudaFuncAttributeMaxDynamicSharedMemorySize, SMEM_TOTAL);

    k_cbprep<<<K_CODES, 256>>>(cb);
    k_zn<<<NROWS / 256, 256>>>(z);
    k_zero<<<1, 1>>>();
    k_argmin<<<NROWS / ROWS_CTA, 256, SMEM_TOTAL>>>(z);
    k_refine<<<NROWS / 16, 256>>>(z, cb);
    k_out<<<NROWS / 256, 256>>>(z, cb, out, out_size);
    k_fin<<<1, 1>>>(out, out_size);
}

// round 12
// speedup vs baseline: 3.2071x; 2.3008x over previous
#include <cuda_runtime.h>
#include <cuda_bf16.h>
#include <cstdint>

#define K_CODES 8192
#define CDIM    256
#define SPAT    4096
#define NROWS   32768
#define OUT_ELEMS (8 * CDIM * SPAT)

#define ROWS_CTA 64
#define PANEL    64                    // codes per tile
#define T_TILES  (K_CODES / PANEL)     // 128
#define A_SPLIT  32768                 // 64 rows * 512 B (staging only)
#define BP_SPLIT 32768                 // 64 codes * 512 B
#define BBUF     (2 * BP_SPLIT)        // 64 KB per buffer (2 splits)
#define SM_CBN   (2 * BBUF)            // 2 x 256 B
#define SMEM_TOTAL (SM_CBN + 512)

typedef unsigned long long ull;

// ---- scratch ----
__device__ uint4  g_c0[K_CODES * CDIM / 8];   // bf16 splits, [code][k] contiguous
__device__ uint4  g_c1[K_CODES * CDIM / 8];
__device__ float  g_cbn[K_CODES];
__device__ float  g_zn[NROWS];
__device__ int    g_cand[NROWS * 16];
__device__ int    g_idx[NROWS];
__device__ double g_loss;

// ---------------- PTX helpers ----------------
__device__ __forceinline__ uint32_t smem_u32(const void* p) {
    uint32_t a;
    asm("{ .reg .u64 t; cvta.to.shared.u64 t, %1; cvt.u32.u64 %0, t; }" : "=r"(a) : "l"(p));
    return a;
}
#define CP16(dst, src) asm volatile("cp.async.cg.shared.global [%0], [%1], 16;" :: "r"(dst), "l"(src))
#define CP_COMMIT()    asm volatile("cp.async.commit_group;" ::: "memory")
#define CP_WAIT0()     asm volatile("cp.async.wait_group 0;" ::: "memory")

__device__ __forceinline__ void ldsm4(uint32_t& r0, uint32_t& r1, uint32_t& r2, uint32_t& r3,
                                      uint32_t addr) {
    asm volatile("ldmatrix.sync.aligned.m8n8.x4.shared.b16 {%0,%1,%2,%3}, [%4];"
                 : "=r"(r0), "=r"(r1), "=r"(r2), "=r"(r3) : "r"(addr));
}
__device__ __forceinline__ void mma_bf16(float* c, uint32_t a0, uint32_t a1, uint32_t a2,
                                         uint32_t a3, uint32_t b0, uint32_t b1) {
    asm volatile(
        "mma.sync.aligned.m16n8k16.row.col.f32.bf16.bf16.f32 "
        "{%0,%1,%2,%3}, {%4,%5,%6,%7}, {%8,%9}, {%0,%1,%2,%3};"
        : "+f"(c[0]), "+f"(c[1]), "+f"(c[2]), "+f"(c[3])
        : "r"(a0), "r"(a1), "r"(a2), "r"(a3), "r"(b0), "r"(b1));
}

// ---------------- K1: codebook 2-way split + norms ----------------
__global__ void k_cbprep(const float* __restrict__ cb) {
    int k = blockIdx.x, c = threadIdx.x;
    float v = cb[k * CDIM + c];
    __nv_bfloat16 c0 = __float2bfloat16_rn(v);
    float r1 = v - __bfloat162float(c0);
    __nv_bfloat16 c1 = __float2bfloat16_rn(r1);
    ((__nv_bfloat16*)g_c0)[k * CDIM + c] = c0;
    ((__nv_bfloat16*)g_c1)[k * CDIM + c] = c1;
    float s = v * v;
    #pragma unroll
    for (int o = 16; o > 0; o >>= 1) s += __shfl_xor_sync(~0u, s, o);
    __shared__ float ws[8];
    if ((c & 31) == 0) ws[c >> 5] = s;
    __syncthreads();
    if (c == 0) {
        float t = 0.f;
        #pragma unroll
        for (int i = 0; i < 8; i++) t += ws[i];
        g_cbn[k] = t;
    }
}

// ---------------- K2: z row norms ----------------
__global__ void k_zn(const float* __restrict__ z) {
    int n = blockIdx.x * 256 + threadIdx.x;
    int b = n >> 12, p = n & 4095;
    const float* zp = z + (size_t)b * CDIM * SPAT + p;
    float s = 0.f;
    #pragma unroll 8
    for (int c = 0; c < CDIM; c++) {
        float v = zp[(size_t)c * SPAT];
        s = fmaf(v, v, s);
    }
    g_zn[n] = s;
}

__global__ void k_zero() { g_loss = 0.0; }

// ---- issue one B panel (tile t, 64 codes, 2 splits) + cbn slice ----
__device__ __forceinline__ void issue_panel(int t, uint32_t dstB, uint32_t dstCbn, int tid) {
    #pragma unroll
    for (int j = 0; j < 16; j++) {
        int id = j * 256 + tid;            // 0..4095
        int sp = id >> 11;
        int rem = id & 2047;
        int code = rem >> 5;
        int kc = (rem & 31) << 4;
        const char* base = sp ? (const char*)g_c1 : (const char*)g_c0;
        const char* src = base + (size_t)(t * PANEL + code) * 512 + kc;
        uint32_t dst = dstB + sp * BP_SPLIT + code * 512 + (kc ^ ((code & 7) << 4));
        CP16(dst, src);
    }
    if (tid < 16)
        CP16(dstCbn + tid * 16, (const char*)g_cbn + (size_t)t * 256 + tid * 16);
}

#define UPD(dv, col, d1, k1, d2, k2) \
    do { if ((dv) < (d1)) { d2 = d1; k2 = k1; d1 = (dv); k1 = (col); } \
         else if ((dv) < (d2)) { d2 = (dv); k2 = (col); } } while (0)

// ---------------- K3: HMMA GEMM, A resident in registers ----------------
__global__ void __launch_bounds__(256, 1)
k_argmin(const float* __restrict__ z) {
    extern __shared__ char smem[];
    uint32_t sb = smem_u32(smem);
    int tid = threadIdx.x, w = tid >> 5, lane = tid & 31;
    int n0 = blockIdx.x * ROWS_CTA;
    int b = n0 >> 12, p0 = n0 & 4095;

    // ---- stage A (2-split, swizzled) into buffer-0 region ----
    {
        int row = tid & 63, kg = tid >> 6;
        const float* zp = z + ((size_t)b * CDIM + kg * 64) * SPAT + p0 + row;
        uint32_t sw = (uint32_t)(row & 7) << 4;
        char* ab = smem + row * 512;
        #pragma unroll 4
        for (int kk = 0; kk < 64; kk += 2) {
            float v0 = zp[(size_t)kk * SPAT];
            float v1 = zp[(size_t)(kk + 1) * SPAT];
            __nv_bfloat16 a0 = __float2bfloat16_rn(v0);
            float ra = v0 - __bfloat162float(a0);
            __nv_bfloat16 a1 = __float2bfloat16_rn(ra);
            __nv_bfloat16 c0 = __float2bfloat16_rn(v1);
            float rc = v1 - __bfloat162float(c0);
            __nv_bfloat16 c1 = __float2bfloat16_rn(rc);
            uint32_t off = (uint32_t)((kg * 64 + kk) * 2) ^ sw;
            *(uint32_t*)(ab + off) =
                (uint32_t)__bfloat16_as_ushort(a0) | ((uint32_t)__bfloat16_as_ushort(c0) << 16);
            *(uint32_t*)(ab + A_SPLIT + off) =
                (uint32_t)__bfloat16_as_ushort(a1) | ((uint32_t)__bfloat16_as_ushort(c1) << 16);
        }
    }
    __syncthreads();

    // ---- load all A fragments into registers (2 splits x 16 ksteps x 4) ----
    int rowAf = 16 * (w & 3) + (lane & 7) + ((lane >> 3) & 1) * 8;
    uint32_t aOff = (uint32_t)rowAf * 512;
    uint32_t swA = (uint32_t)(rowAf & 7) << 4;
    uint32_t kadd = (uint32_t)(lane >> 4) * 16;
    uint32_t azf[2][16][4];
    #pragma unroll
    for (int s = 0; s < 2; s++)
        #pragma unroll
        for (int ks = 0; ks < 16; ks++)
            ldsm4(azf[s][ks][0], azf[s][ks][1], azf[s][ks][2], azf[s][ks][3],
                  sb + s * A_SPLIT + aOff + (((uint32_t)(ks * 32) + kadd) ^ swA));
    __syncthreads();

    // ---- preload panel 0 into buffer 0 (overwrites A staging; frags in regs) ----
    issue_panel(0, sb, sb + SM_CBN, tid);
    CP_COMMIT();

    int half = w >> 2;
    int rowBf = 32 * half + (lane & 7) + ((lane >> 3) & 1) * 8;
    uint32_t bOff1 = (uint32_t)rowBf * 512;
    uint32_t bOff2 = bOff1 + 16 * 512;
    uint32_t swB = (uint32_t)(rowBf & 7) << 4;

    int rA = 16 * (w & 3) + (lane >> 2);
    float ZA = g_zn[n0 + rA], ZB = g_zn[n0 + rA + 8];
    float dA1 = 3.4e38f, dA2 = 3.4e38f, dB1 = 3.4e38f, dB2 = 3.4e38f;
    int   kA1 = 0, kA2 = 0, kB1 = 0, kB2 = 0;

    float acc[4][4];
    #pragma unroll
    for (int i = 0; i < 4; i++)
        #pragma unroll
        for (int j = 0; j < 4; j++) acc[i][j] = 0.f;

    #pragma unroll 1
    for (int t = 0; t < T_TILES; t++) {
        int buf = t & 1;
        CP_WAIT0();
        __syncthreads();
        if (t + 1 < T_TILES) {
            issue_panel(t + 1, sb + (buf ^ 1) * BBUF, sb + SM_CBN + (buf ^ 1) * 256, tid);
            CP_COMMIT();
        }
        uint32_t Bb = sb + buf * BBUF;

        // passes: (z0,c0), (z0,c1), (z1,c0)
        #pragma unroll
        for (int p = 0; p < 3; p++) {
            const int sa = (p >> 1);          // 0,0,1
            const int scb = (p & 1);          // 0,1,0
            uint32_t bSp = Bb + scb * BP_SPLIT;
            #pragma unroll
            for (int ks = 0; ks < 16; ks++) {
                uint32_t colB = ((uint32_t)(ks * 32) + kadd) ^ swB;
                uint32_t b0, b1, b2, b3, b4, b5, b6, b7;
                ldsm4(b0, b1, b2, b3, bSp + bOff1 + colB);
                ldsm4(b4, b5, b6, b7, bSp + bOff2 + colB);
                mma_bf16(acc[0], azf[sa][ks][0], azf[sa][ks][1], azf[sa][ks][2], azf[sa][ks][3], b0, b2);
                mma_bf16(acc[1], azf[sa][ks][0], azf[sa][ks][1], azf[sa][ks][2], azf[sa][ks][3], b1, b3);
                mma_bf16(acc[2], azf[sa][ks][0], azf[sa][ks][1], azf[sa][ks][2], azf[sa][ks][3], b4, b6);
                mma_bf16(acc[3], azf[sa][ks][0], azf[sa][ks][1], azf[sa][ks][2], azf[sa][ks][3], b5, b7);
            }
        }

        // ---- epilogue: approx d, top-2 per lane ----
        {
            const float* cbn = (const float*)(smem + SM_CBN + buf * 256);
            int cloc = 32 * half + (lane & 3) * 2;
            #pragma unroll
            for (int f = 0; f < 4; f++) {
                float cnx = cbn[cloc + f * 8];
                float cny = cbn[cloc + f * 8 + 1];
                int col = t * PANEL + cloc + f * 8;
                float d;
                d = __fmaf_rn(-2.f, acc[f][0], __fadd_rn(ZA, cnx));
                UPD(d, col, dA1, kA1, dA2, kA2);
                d = __fmaf_rn(-2.f, acc[f][1], __fadd_rn(ZA, cny));
                UPD(d, col + 1, dA1, kA1, dA2, kA2);
                d = __fmaf_rn(-2.f, acc[f][2], __fadd_rn(ZB, cnx));
                UPD(d, col, dB1, kB1, dB2, kB2);
                d = __fmaf_rn(-2.f, acc[f][3], __fadd_rn(ZB, cny));
                UPD(d, col + 1, dB1, kB1, dB2, kB2);
                acc[f][0] = acc[f][1] = acc[f][2] = acc[f][3] = 0.f;
            }
        }
    }

    // ---- write candidates: 16 per row ----
    {
        int baseA = (n0 + rA) * 16 + half * 8 + (lane & 3) * 2;
        g_cand[baseA]     = kA1;
        g_cand[baseA + 1] = kA2;
        int baseB = (n0 + rA + 8) * 16 + half * 8 + (lane & 3) * 2;
        g_cand[baseB]     = kB1;
        g_cand[baseB + 1] = kB2;
    }
}

// ---------------- K3b: exact fp32 refinement (R2-proven semantics) --------
__global__ void __launch_bounds__(256, 2)
k_refine(const float* __restrict__ z, const float* __restrict__ cb) {
    __shared__ float zs[16][256];
    int tid = threadIdx.x;
    int n0 = blockIdx.x * 16;
    int b = n0 >> 12, p0 = n0 & 4095;

    for (int i = tid; i < 16 * 256; i += 256) {
        int c = i >> 4, pr = i & 15;
        zs[pr][c] = z[((size_t)b * CDIM + c) * SPAT + p0 + pr];
    }
    __syncthreads();

    int r = tid >> 4;
    int ci = tid & 15;
    int n = n0 + r;
    int k = g_cand[n * 16 + ci];

    const float4* cbr = (const float4*)(cb + (size_t)k * CDIM);
    const float4* zr = (const float4*)zs[r];
    float acc = 0.f;
    #pragma unroll 8
    for (int c4 = 0; c4 < 64; c4++) {
        float4 bv = cbr[c4];
        float4 av = zr[c4];
        acc = fmaf(av.x, bv.x, acc);
        acc = fmaf(av.y, bv.y, acc);
        acc = fmaf(av.z, bv.z, acc);
        acc = fmaf(av.w, bv.w, acc);
    }
    float t1 = __fadd_rn(g_zn[n], g_cbn[k]);
    float d = __fmaf_rn(-2.f, acc, t1);

    #pragma unroll
    for (int o = 8; o > 0; o >>= 1) {
        float od = __shfl_xor_sync(~0u, d, o, 16);
        int   ok = __shfl_xor_sync(~0u, k, o, 16);
        if (od < d || (od == d && ok < k)) { d = od; k = ok; }
    }
    if (ci == 0) g_idx[n] = k;
}

// ---------------- K4: gather output + loss ----------------
__global__ void k_out(const float* __restrict__ z, const float* __restrict__ cb,
                      float* __restrict__ out, int out_size) {
    int n = blockIdx.x * 256 + threadIdx.x;
    int b = n >> 12, p = n & 4095;
    int myk = g_idx[n];
    const float* crow = cb + (size_t)myk * CDIM;
    const float* zp = z + (size_t)b * CDIM * SPAT + p;
    float* op = out + (size_t)b * CDIM * SPAT + p;
    double ls = 0.0;
    #pragma unroll 4
    for (int c = 0; c < CDIM; c++) {
        float q = crow[c];
        float zv = zp[(size_t)c * SPAT];
        op[(size_t)c * SPAT] = q;
        float dlt = q - zv;
        ls += (double)dlt * (double)dlt;
    }
    #pragma unroll
    for (int o = 16; o > 0; o >>= 1) ls += __shfl_xor_sync(~0u, ls, o);
    __shared__ double ws[8];
    if ((threadIdx.x & 31) == 0) ws[threadIdx.x >> 5] = ls;
    __syncthreads();
    if (threadIdx.x == 0) {
        double t = 0.0;
        #pragma unroll
        for (int i = 0; i < 8; i++) t += ws[i];
        atomicAdd(&g_loss, t);
    }
    if (out_size >= OUT_ELEMS + 1 + NROWS)
        out[OUT_ELEMS + 1 + n] = (float)myk;
}

__global__ void k_fin(float* __restrict__ out, int out_size) {
    if (out_size >= OUT_ELEMS + 1)
        out[OUT_ELEMS] = (float)((2.0 * g_loss) / (double)OUT_ELEMS);
}

extern "C" void kernel_launch(void* const* d_in, const int* in_sizes, int n_in,
                              void* d_out, int out_size) {
    const float* z  = (const float*)d_in[0];
    const float* cb = (const float*)d_in[1];
    if (n_in >= 2 && in_sizes[0] == K_CODES * CDIM) {
        z  = (const float*)d_in[1];
        cb = (const float*)d_in[0];
    }
    float* out = (float*)d_out;

    cudaFuncSetAttribute(k_argmin, cudaFuncAttributeMaxDynamicSharedMemorySize, SMEM_TOTAL);

    k_cbprep<<<K_CODES, 256>>>(cb);
    k_zn<<<NROWS / 256, 256>>>(z);
    k_zero<<<1, 1>>>();
    k_argmin<<<NROWS / ROWS_CTA, 256, SMEM_TOTAL>>>(z);
    k_refine<<<NROWS / 16, 256>>>(z, cb);
    k_out<<<NROWS / 256, 256>>>(z, cb, out, out_size);
    k_fin<<<1, 1>>>(out, out_size);
}